// round 3
// baseline (speedup 1.0000x reference)
#include <cuda_runtime.h>

typedef unsigned long long ull;

#define BS   8
#define NPTS 1024
#define JJ   3
#define FIN  32
#define KIN  96
#define FOUT 64
#define ROWS (BS*NPTS)
#define MC   16
#define NCHUNK (NPTS/MC)
#define PWW  50
#define PX2  17
#define BLKN 64
#define NTILE (NPTS/BLKN)
#define PYT  66

__device__ __align__(16) float g_y[ROWS*KIN];
__device__ __align__(16) float g_wt[KIN*FOUT];
__device__ float g_psum[(ROWS/64)*FOUT];
__device__ float g_psq [(ROWS/64)*FOUT];
__device__ float g_coef[2*FOUT];

__device__ __forceinline__ ull fma2(ull a, ull b, ull c) {
    ull d;
    asm("fma.rn.f32x2 %0, %1, %2, %3;" : "=l"(d) : "l"(a), "l"(b), "l"(c));
    return d;
}
__device__ __forceinline__ ull ld64s(const float* p) {
    return *reinterpret_cast<const ull*>(p);
}
__device__ __forceinline__ float hsum2(ull v) {
    union { ull u; float f[2]; } cv; cv.u = v;
    return cv.f[0] + cv.f[1];
}
__device__ __forceinline__ ull dup2(float x) {
    unsigned b = __float_as_uint(x);
    return (((ull)b) << 32) | (ull)b;
}

// K0: fuse/transpose W1,W2 -> g_wt[k][col]
__global__ void k0_wt(const float* __restrict__ W1, const float* __restrict__ W2) {
    int t = blockIdx.x * 256 + threadIdx.x;
    if (t < KIN * FOUT) {
        int c = t & 63, k = t >> 6;
        g_wt[k * FOUT + c] = (c < 32) ? W1[c * KIN + k] : W2[(c - 32) * KIN + k];
    }
}

// K1: y[b,n,j,f] = sum_m WW[b,n,m,j] * x[b,m,f]
__global__ __launch_bounds__(256) void k1_gmul(const float* __restrict__ WW,
                                               const float* __restrict__ X) {
    __shared__ __align__(16) float ww_s[BLKN * PWW];   // [n][j*MC+m]
    __shared__ __align__(16) ull   x2_s[FIN * PX2];    // [f][m-pair]

    const int t  = threadIdx.x;
    const int b  = blockIdx.y;
    const int n0 = blockIdx.x * BLKN;
    const float* wwB = WW + (size_t)(b * NPTS + n0) * (NPTS * JJ);
    const float* xB  = X + (size_t)b * NPTS * FIN;

    const int lane = t & 31, warp = t >> 5;
    const int fq = lane & 7, nq = lane >> 3;
    const int nloc = warp * 8 + nq * 2;

    ull acc[2][3][4];
#pragma unroll
    for (int a = 0; a < 2; a++)
#pragma unroll
        for (int j = 0; j < 3; j++)
#pragma unroll
            for (int k = 0; k < 4; k++) acc[a][j][k] = 0ULL;

    int goff[3], soff[3][4];
#pragma unroll
    for (int i = 0; i < 3; i++) {
        int flat = i * 256 + t;
        int n = flat / 12, mj4 = flat % 12;
        goff[i] = n * (NPTS * JJ) + mj4 * 4;
#pragma unroll
        for (int k = 0; k < 4; k++) {
            int mj = mj4 * 4 + k;
            int m = mj / 3, j = mj - m * 3;
            soff[i][k] = n * PWW + j * MC + m;
        }
    }
    const bool xact = t < 128;
    const int  xm = t >> 3, xf = (t & 7) * 4;
    const int  xgoff = xm * FIN + xf;
    int xsoff[4];
#pragma unroll
    for (int k = 0; k < 4; k++)
        xsoff[k] = ((xf + k) * PX2 + (xm >> 1)) * 2 + (xm & 1);

    float4 wr0, wr1, wr2, xr;
    wr0 = *(const float4*)(wwB + goff[0]);
    wr1 = *(const float4*)(wwB + goff[1]);
    wr2 = *(const float4*)(wwB + goff[2]);
    xr  = xact ? *(const float4*)(xB + xgoff) : make_float4(0.f,0.f,0.f,0.f);

    for (int c = 0; c < NCHUNK; ++c) {
        ww_s[soff[0][0]] = wr0.x; ww_s[soff[0][1]] = wr0.y;
        ww_s[soff[0][2]] = wr0.z; ww_s[soff[0][3]] = wr0.w;
        ww_s[soff[1][0]] = wr1.x; ww_s[soff[1][1]] = wr1.y;
        ww_s[soff[1][2]] = wr1.z; ww_s[soff[1][3]] = wr1.w;
        ww_s[soff[2][0]] = wr2.x; ww_s[soff[2][1]] = wr2.y;
        ww_s[soff[2][2]] = wr2.z; ww_s[soff[2][3]] = wr2.w;
        if (xact) {
            float* xs = reinterpret_cast<float*>(x2_s);
            xs[xsoff[0]] = xr.x; xs[xsoff[1]] = xr.y;
            xs[xsoff[2]] = xr.z; xs[xsoff[3]] = xr.w;
        }
        __syncthreads();

        if (c + 1 < NCHUNK) {
            const float* p = wwB + (c + 1) * (MC * JJ);
            wr0 = *(const float4*)(p + goff[0]);
            wr1 = *(const float4*)(p + goff[1]);
            wr2 = *(const float4*)(p + goff[2]);
            if (xact) xr = *(const float4*)(xB + (c + 1) * MC * FIN + xgoff);
        }

#pragma unroll
        for (int mp = 0; mp < MC / 2; ++mp) {
            ull xv[4];
#pragma unroll
            for (int k = 0; k < 4; k++)
                xv[k] = x2_s[(fq + 8 * k) * PX2 + mp];
#pragma unroll
            for (int nn = 0; nn < 2; nn++) {
                const float* rp = ww_s + (nloc + nn) * PWW + 2 * mp;
                ull w0 = ld64s(rp);
                ull w1 = ld64s(rp + MC);
                ull w2 = ld64s(rp + 2 * MC);
#pragma unroll
                for (int k = 0; k < 4; k++) {
                    acc[nn][0][k] = fma2(w0, xv[k], acc[nn][0][k]);
                    acc[nn][1][k] = fma2(w1, xv[k], acc[nn][1][k]);
                    acc[nn][2][k] = fma2(w2, xv[k], acc[nn][2][k]);
                }
            }
        }
        __syncthreads();
    }

    const size_t rowbase = (size_t)(b * NPTS + n0);
#pragma unroll
    for (int nn = 0; nn < 2; nn++) {
        float* yr = g_y + (rowbase + nloc + nn) * KIN;
#pragma unroll
        for (int j = 0; j < 3; j++)
#pragma unroll
            for (int k = 0; k < 4; k++)
                yr[j * FIN + fq + 8 * k] = hsum2(acc[nn][j][k]);
    }
}

// K2: z = [relu(y@W1^T+b1), y@W2^T+b2], write Z, BN partial sums (fixed order)
__global__ __launch_bounds__(256) void k2_mlp(const float* __restrict__ b1,
                                              const float* __restrict__ b2,
                                              float* __restrict__ Z) {
    __shared__ __align__(16) float yT[KIN * PYT];
    __shared__ float ps[4][FOUT];
    __shared__ float pq[4][FOUT];

    const int t = threadIdx.x;
    const int row0 = blockIdx.x * 64;

#pragma unroll
    for (int i = 0; i < 6; i++) {
        int flat = i * 256 + t;
        int r = flat / 24, k4 = flat % 24;
        float4 v = *(const float4*)&g_y[(size_t)(row0 + r) * KIN + k4 * 4];
        int base = (k4 * 4) * PYT + r;
        yT[base]           = v.x;
        yT[base +     PYT] = v.y;
        yT[base + 2 * PYT] = v.z;
        yT[base + 3 * PYT] = v.w;
    }
    __syncthreads();

    const int col = t & 63, rg = t >> 6;
    const int rbase = rg * 16;
    ull acc2[8];
#pragma unroll
    for (int rp = 0; rp < 8; rp++) acc2[rp] = 0ULL;

#pragma unroll 4
    for (int k = 0; k < KIN; k++) {
        ull wd = dup2(__ldg(&g_wt[k * FOUT + col]));
        const float* yp = yT + k * PYT + rbase;
#pragma unroll
        for (int rp = 0; rp < 8; rp++)
            acc2[rp] = fma2(ld64s(yp + 2 * rp), wd, acc2[rp]);
    }

    const float bias = (col < 32) ? __ldg(&b1[col]) : __ldg(&b2[col - 32]);
    float s = 0.f, sq = 0.f;
#pragma unroll
    for (int rp = 0; rp < 8; rp++) {
        union { ull u; float f[2]; } cv; cv.u = acc2[rp];
#pragma unroll
        for (int h = 0; h < 2; h++) {
            float z = cv.f[h] + bias;
            if (col < 32) z = fmaxf(z, 0.f);
            Z[(size_t)(row0 + rbase + 2 * rp + h) * FOUT + col] = z;
            s += z; sq += z * z;
        }
    }
    ps[rg][col] = s; pq[rg][col] = sq;
    __syncthreads();
    if (rg == 0) {
        float S = ps[0][col] + ps[1][col] + ps[2][col] + ps[3][col];
        float Q = pq[0][col] + pq[1][col] + pq[2][col] + pq[3][col];
        g_psum[blockIdx.x * FOUT + col] = S;
        g_psq [blockIdx.x * FOUT + col] = Q;
    }
}

// K3: reduce partials -> scale/shift (single block, fixed order)
__global__ void k3_stats(const float* __restrict__ gamma, const float* __restrict__ beta) {
    int c = threadIdx.x;   // 64 threads
    float S = 0.f, Q = 0.f;
    for (int i = 0; i < ROWS / 64; i++) {
        S += g_psum[i * FOUT + c];
        Q += g_psq [i * FOUT + c];
    }
    float mean = S * (1.0f / ROWS);
    float var  = Q * (1.0f / ROWS) - mean * mean;
    float sc   = gamma[c] * rsqrtf(var + 1e-5f);
    g_coef[c]        = sc;
    g_coef[FOUT + c] = beta[c] - mean * sc;
}

// K4: in-place normalize
__global__ __launch_bounds__(256) void k4_norm(float* __restrict__ Z) {
    int idx = blockIdx.x * 256 + threadIdx.x;   // float4 index
    float4 v = ((float4*)Z)[idx];
    int c = (idx & 15) * 4;
    v.x = v.x * g_coef[c]     + g_coef[FOUT + c];
    v.y = v.y * g_coef[c + 1] + g_coef[FOUT + c + 1];
    v.z = v.z * g_coef[c + 2] + g_coef[FOUT + c + 2];
    v.w = v.w * g_coef[c + 3] + g_coef[FOUT + c + 3];
    ((float4*)Z)[idx] = v;
}

extern "C" void kernel_launch(void* const* d_in, const int* in_sizes, int n_in,
                              void* d_out, int out_size) {
    const float* WW    = (const float*)d_in[0];
    const float* X     = (const float*)d_in[1];
    const float* W1    = (const float*)d_in[2];
    const float* b1    = (const float*)d_in[3];
    const float* W2    = (const float*)d_in[4];
    const float* b2    = (const float*)d_in[5];
    const float* gamma = (const float*)d_in[6];
    const float* beta  = (const float*)d_in[7];
    float* Z = (float*)d_out;

    k0_wt<<<(KIN * FOUT + 255) / 256, 256>>>(W1, W2);
    dim3 g1(NTILE, BS);
    k1_gmul<<<g1, 256>>>(WW, X);
    k2_mlp<<<ROWS / 64, 256>>>(b1, b2, Z);
    k3_stats<<<1, 64>>>(gamma, beta);
    k4_norm<<<(ROWS * FOUT / 4) / 256, 256>>>(Z);
}